// round 11
// baseline (speedup 1.0000x reference)
#include <cuda_runtime.h>
#include <cuda_bf16.h>
#include <cstdint>

#define Hdim 128
#define Odim 32
#define INdim 64
#define RB 8
#define NTHR 128
#define MAXB 16384
#define MAXLVL 6

__device__ float g_H0 [(size_t)MAXB * Hdim];
__device__ float g_HAI[(size_t)MAXLVL * MAXB * Hdim];
__device__ float g_H2 [(size_t)MAXLVL * MAXB * Hdim];
__device__ float g_PR [(size_t)(MAXLVL + 1) * MAXB * Odim];

#define OFF_WH_F 0
#define OFF_WI_F 49152
#define OFF_UF   61440
#define OFF_UA   77824
__device__ float g_WP[94208];
__device__ float g_WPRED[4096];
__device__ __align__(1024) unsigned char g_WTC[327680];

typedef unsigned long long u64;
union F4U { float4 f; ulonglong2 u; };

__device__ __forceinline__ void ffma2(u64& d, u64 a, u64 b) {
    asm volatile("fma.rn.f32x2 %0, %1, %2, %0;" : "+l"(d) : "l"(a), "l"(b));
}
__device__ __forceinline__ u64 pack2(float lo, float hi) {
    u64 r; asm("mov.b64 %0, {%1, %2};" : "=l"(r) : "f"(lo), "f"(hi)); return r;
}
__device__ __forceinline__ float f2sum(u64 v) {
    float lo, hi; asm("mov.b64 {%0, %1}, %2;" : "=f"(lo), "=f"(hi) : "l"(v));
    return lo + hi;
}
__device__ __forceinline__ float sigmoidf_(float x) { return 1.0f / (1.0f + expf(-x)); }
__device__ __forceinline__ uint32_t smem_u32(const void* p) {
    uint32_t a;
    asm("{ .reg .u64 t; cvta.to.shared.u64 t, %1; cvt.u32.u64 %0, t; }" : "=r"(a) : "l"(p));
    return a;
}
__device__ __forceinline__ void ldsm4(uint32_t* r, uint32_t a) {
    asm volatile("ldmatrix.sync.aligned.m8n8.x4.shared.b16 {%0,%1,%2,%3}, [%4];"
        : "=r"(r[0]),"=r"(r[1]),"=r"(r[2]),"=r"(r[3]) : "r"(a));
}
__device__ __forceinline__ void mma16816(float* c, const uint32_t* a, const uint32_t* b) {
    asm volatile("mma.sync.aligned.m16n8k16.row.col.f32.bf16.bf16.f32 "
        "{%0,%1,%2,%3}, {%4,%5,%6,%7}, {%8,%9}, {%0,%1,%2,%3};"
        : "+f"(c[0]),"+f"(c[1]),"+f"(c[2]),"+f"(c[3])
        : "r"(a[0]),"r"(a[1]),"r"(a[2]),"r"(a[3]),"r"(b[0]),"r"(b[1]));
}
#define CPA16(d, s) asm volatile("cp.async.cg.shared.global [%0], [%1], 16;" :: "r"(d), "l"(s))
#define CPCOMMIT()  asm volatile("cp.async.commit_group;")
#define CPWAIT0()   asm volatile("cp.async.wait_group 0;")

__device__ __forceinline__ void pack_one(const float* __restrict__ s, float* __restrict__ d, int g) {
    int k4 = g >> 7, j = g & 127;
    float4 v;
    v.x = s[(size_t)(4*k4+0)*128+j]; v.y = s[(size_t)(4*k4+1)*128+j];
    v.z = s[(size_t)(4*k4+2)*128+j]; v.w = s[(size_t)(4*k4+3)*128+j];
    *reinterpret_cast<float4*>(d + (size_t)g*4) = v;
}
__global__ void pack_kernel(const float* __restrict__ fwh, const float* __restrict__ fwi,
                            const float* __restrict__ ufw, const float* __restrict__ uaw,
                            const float* __restrict__ h2o_w,
                            float* __restrict__ WP, float* __restrict__ WPRED) {
    int g = blockIdx.x * blockDim.x + threadIdx.x;
    if      (g < 12288) pack_one(fwh, WP + OFF_WH_F, g);
    else if (g < 15360) pack_one(fwi, WP + OFF_WI_F, g - 12288);
    else if (g < 19456) pack_one(ufw, WP + OFF_UF,   g - 15360);
    else if (g < 23552) pack_one(uaw, WP + OFF_UA,   g - 19456);
    else if (g < 25600) {
        int g2 = g - 23552, k2 = g2 >> 5, o = g2 & 31;
        WPRED[g2*2]   = h2o_w[(size_t)(2*k2)*32+o];
        WPRED[g2*2+1] = h2o_w[(size_t)(2*k2+1)*32+o];
    }
}
__global__ void pack_wtc(const float* __restrict__ awh, const float* __restrict__ awi,
                         unsigned char* __restrict__ WTC) {
    int id = blockIdx.x * blockDim.x + threadIdx.x;
    if (id >= 2560) return;
    int c = id / 512, n = id % 512;
    int gate = n >> 7, j = n & 127;
    for (int kk = 0; kk < 32; kk++) {
        int gk = c*32 + kk;
        float w;
        if      (gate == 0) w = gk < 128 ? awh[(size_t)gk*128 + j] : awi[(size_t)(gk-128)*128 + j];
        else if (gate == 1) w = gk < 128 ? awh[16384 + (size_t)gk*128 + j] : awi[4096 + (size_t)(gk-128)*128 + j];
        else if (gate == 2) w = gk < 128 ? awh[32768 + (size_t)gk*128 + j] : 0.0f;
        else                w = gk < 128 ? 0.0f : awi[8192 + (size_t)(gk-128)*128 + j];
        __nv_bfloat16 hi = __float2bfloat16(w);
        __nv_bfloat16 lo = __float2bfloat16(w - __bfloat162float(hi));
        size_t off = (size_t)c*32768 + (size_t)n*64 + kk*2;
        *(__nv_bfloat16*)(WTC + off)          = hi;
        *(__nv_bfloat16*)(WTC + 163840 + off) = lo;
    }
}

__global__ void __launch_bounds__(NTHR)
init_kernel(const float* __restrict__ z, const float* __restrict__ w,
            const float* __restrict__ b, float* __restrict__ hout) {
    __shared__ float zs[RB][INdim];
    const int j = threadIdx.x, row0 = blockIdx.x * RB;
    {
        const float4* src = reinterpret_cast<const float4*>(z + (size_t)row0 * INdim);
        float4* dst = reinterpret_cast<float4*>(&zs[0][0]);
        for (int i = j; i < RB * INdim / 4; i += NTHR) dst[i] = src[i];
    }
    __syncthreads();
    const float bb = b[j];
    float acc[RB];
#pragma unroll
    for (int i = 0; i < RB; i++) acc[i] = bb;
#pragma unroll 4
    for (int k = 0; k < INdim; k += 4) {
        float4 hv[RB];
#pragma unroll
        for (int i = 0; i < RB; i++) hv[i] = *reinterpret_cast<const float4*>(&zs[i][k]);
#pragma unroll
        for (int kk = 0; kk < 4; kk++) {
            float wv = w[(size_t)(k+kk)*Hdim + j];
#pragma unroll
            for (int i = 0; i < RB; i++) {
                float h = (kk==0)?hv[i].x:(kk==1)?hv[i].y:(kk==2)?hv[i].z:hv[i].w;
                acc[i] += h * wv;
            }
        }
    }
#pragma unroll
    for (int i = 0; i < RB; i++) hout[(size_t)(row0+i)*Hdim + j] = acc[i];
}

// ======== mma.sync node kernel: M=32, 256 thr, 2 CTA/SM ========
#define SM_AHI  0
#define SM_ALO  10752
#define SM_B    21504
#define SMEM_TC 62464
#define APITCH  336

__global__ void __launch_bounds__(256, 2)
node_tc(const float* __restrict__ h_a,
        const float* __restrict__ wpred, const float* __restrict__ h2o_b,
        const unsigned char* __restrict__ WTC,
        const float* __restrict__ abi, const float* __restrict__ abh,
        float* __restrict__ pred_out, float* __restrict__ probs_out,
        float* __restrict__ h_out) {
    extern __shared__ __align__(128) unsigned char smem[];
    const uint32_t sb = smem_u32(smem);
    const int t = threadIdx.x, wid = t >> 5, lane = t & 31;
    const int row0 = blockIdx.x * 32;

    for (int i = t; i < 1024; i += 256) {  // h -> A hi/lo, cols 0-127
        int row = i >> 5, k4 = i & 31;
        float4 v = ((const float4*)(h_a + (size_t)(row0+row)*Hdim))[k4];
        __nv_bfloat162 h01 = __floats2bfloat162_rn(v.x, v.y);
        __nv_bfloat162 h23 = __floats2bfloat162_rn(v.z, v.w);
        __nv_bfloat162 l01 = __floats2bfloat162_rn(v.x-__bfloat162float(h01.x), v.y-__bfloat162float(h01.y));
        __nv_bfloat162 l23 = __floats2bfloat162_rn(v.z-__bfloat162float(h23.x), v.w-__bfloat162float(h23.y));
        uint32_t o = (uint32_t)row*APITCH + k4*8;
        *(__nv_bfloat162*)(smem + SM_AHI + o)     = h01;
        *(__nv_bfloat162*)(smem + SM_AHI + o + 4) = h23;
        *(__nv_bfloat162*)(smem + SM_ALO + o)     = l01;
        *(__nv_bfloat162*)(smem + SM_ALO + o + 4) = l23;
    }
    {   // pred fp32 + softmax; probs -> A cols 128-159
        const float bo = h2o_b[lane];
        const u64* WPp = (const u64*)wpred;
        for (int rr = 0; rr < 4; rr++) {
            int row = wid*4 + rr, grow = row0 + row;
            const u64* hr = (const u64*)(h_a + (size_t)grow*Hdim);
            u64 acc = pack2(bo, 0.0f);
#pragma unroll 8
            for (int k2 = 0; k2 < 64; k2++) ffma2(acc, hr[k2], WPp[k2*32 + lane]);
            float v = f2sum(acc), m = v;
#pragma unroll
            for (int s = 16; s > 0; s >>= 1) m = fmaxf(m, __shfl_xor_sync(~0u, m, s));
            float e = expf(v - m), ss = e;
#pragma unroll
            for (int s = 16; s > 0; s >>= 1) ss += __shfl_xor_sync(~0u, ss, s);
            float p = e / ss;
            pred_out[(size_t)grow*Odim + lane]  = v;
            probs_out[(size_t)grow*Odim + lane] = p;
            __nv_bfloat16 ph = __float2bfloat16(p);
            __nv_bfloat16 pl = __float2bfloat16(p - __bfloat162float(ph));
            uint32_t o = (uint32_t)row*APITCH + 256 + 2*lane;
            *(__nv_bfloat16*)(smem + SM_AHI + o) = ph;
            *(__nv_bfloat16*)(smem + SM_ALO + o) = pl;
        }
    }

    const int wm = wid & 1, wn = wid >> 1;
    float acc[16][4];
#pragma unroll
    for (int i = 0; i < 16; i++)
#pragma unroll
        for (int q = 0; q < 4; q++) acc[i][q] = 0.0f;

    const uint32_t abase = sb + SM_AHI + (uint32_t)(wm*16 + (lane & 15))*APITCH + (uint32_t)(lane >> 4)*16;
    const uint32_t bln4  = (uint32_t)(lane & 7)*80u + (uint32_t)((lane >> 3) & 1)*16u + (uint32_t)(lane >> 4)*640u;

    for (int p = 0; p < 10; p++) {
        int c = p >> 1, pl = p & 1;
        const unsigned char* src = WTC + (size_t)pl*163840 + (size_t)c*32768;
#pragma unroll
        for (int r2 = 0; r2 < 2; r2++) {
            int n = t + r2*256;
            uint32_t dst = sb + SM_B + (uint32_t)n*80u;
            const unsigned char* s0 = src + (size_t)n*64;
#pragma unroll
            for (int q = 0; q < 4; q++) CPA16(dst + q*16, s0 + q*16);
        }
        CPCOMMIT(); CPWAIT0();
        __syncthreads();
#pragma unroll
        for (int kk = 0; kk < 2; kk++) {
            uint32_t ah[4], al[4];
            ldsm4(ah, abase + (uint32_t)(c*32 + kk*16)*2);
            if (!pl) ldsm4(al, abase + 10752u + (uint32_t)(c*32 + kk*16)*2);
#pragma unroll
            for (int t8 = 0; t8 < 8; t8++) {
                uint32_t b[4];
                ldsm4(b, sb + SM_B + (uint32_t)(wn*128 + t8*16)*80u + bln4 + (uint32_t)kk*32);
                mma16816(acc[2*t8],   ah, b);
                mma16816(acc[2*t8+1], ah, b+2);
                if (!pl) {
                    mma16816(acc[2*t8],   al, b);
                    mma16816(acc[2*t8+1], al, b+2);
                }
            }
        }
        __syncthreads();
    }

    // epilogue: two-pass gate exchange through smem overlay (32 rows x 132 pitch)
    float* exch = (float*)smem;
    const int r1 = wm*16 + (lane >> 2);
    const int row = t >> 3, j0 = (t & 7)*16;
    float rg[16], zg[16];

    if (wn < 2) {
        int base = wn*4224;
#pragma unroll
        for (int t16 = 0; t16 < 16; t16++) {
            int jj = t16*8 + 2*(lane & 3);
            *(float2*)&exch[base + r1*132 + jj]     = make_float2(acc[t16][0], acc[t16][1]);
            *(float2*)&exch[base + (r1+8)*132 + jj] = make_float2(acc[t16][2], acc[t16][3]);
        }
    }
    __syncthreads();
#pragma unroll
    for (int b = 0; b < 4; b++) {
        int j = j0 + b*4;
        float4 vr = *(const float4*)&exch[row*132 + j];
        float4 vz = *(const float4*)&exch[4224 + row*132 + j];
        float4 bir = *(const float4*)&abi[j],     bhr = *(const float4*)&abh[j];
        float4 biz = *(const float4*)&abi[128+j], bhz = *(const float4*)&abh[128+j];
        const float* pvr = (const float*)&vr; const float* pvz = (const float*)&vz;
        const float* pbr = (const float*)&bir; const float* phr = (const float*)&bhr;
        const float* pbz = (const float*)&biz; const float* phz = (const float*)&bhz;
#pragma unroll
        for (int e = 0; e < 4; e++) {
            rg[b*4+e] = sigmoidf_(pvr[e] + pbr[e] + phr[e]);
            zg[b*4+e] = sigmoidf_(pvz[e] + pbz[e] + phz[e]);
        }
    }
    __syncthreads();
    if (wn >= 2) {
        int base = (wn-2)*4224;
#pragma unroll
        for (int t16 = 0; t16 < 16; t16++) {
            int jj = t16*8 + 2*(lane & 3);
            *(float2*)&exch[base + r1*132 + jj]     = make_float2(acc[t16][0], acc[t16][1]);
            *(float2*)&exch[base + (r1+8)*132 + jj] = make_float2(acc[t16][2], acc[t16][3]);
        }
    }
    __syncthreads();
#pragma unroll
    for (int b = 0; b < 4; b++) {
        int j = j0 + b*4;
        float4 vh = *(const float4*)&exch[row*132 + j];          // nh
        float4 vx = *(const float4*)&exch[4224 + row*132 + j];   // nx
        float4 bin = *(const float4*)&abi[256+j], bhn = *(const float4*)&abh[256+j];
        float4 hv = *(const float4*)(h_a + (size_t)(row0+row)*Hdim + j);
        float4 out;
        const float* pvh = (const float*)&vh; const float* pvx = (const float*)&vx;
        const float* pbn = (const float*)&bin; const float* phn = (const float*)&bhn;
        const float* phv = (const float*)&hv; float* po = (float*)&out;
#pragma unroll
        for (int e = 0; e < 4; e++) {
            float nn = tanhf(pvx[e] + pbn[e] + rg[b*4+e]*(pvh[e] + phn[e]));
            po[e] = (1.0f - zg[b*4+e])*nn + zg[b*4+e]*phv[e];
        }
        *(float4*)(h_out + (size_t)(row0+row)*Hdim + j) = out;
    }
}

// ======== combine kernel (R5 FFMA2, proven) ========
__device__ __forceinline__ void gru_rows8(
    const float* __restrict__ hsf, const float* __restrict__ psf, int j,
    const float* __restrict__ whP, const float* __restrict__ wiP,
    const float* __restrict__ bi,  const float* __restrict__ bh, float out[RB]) {
    const float br_ = bi[j] + bh[j];
    const float bz_ = bi[128+j] + bh[128+j];
    const float bxn = bi[256+j];
    const float bhn = bh[256+j];
    u64 ar[RB], az[RB], anh[RB], anx[RB];
#pragma unroll
    for (int i = 0; i < RB; i++) {
        ar[i]=pack2(br_,0.f); az[i]=pack2(bz_,0.f); anh[i]=pack2(bhn,0.f); anx[i]=pack2(bxn,0.f);
    }
    const float4* pw = reinterpret_cast<const float4*>(whP) + j;
    const ulonglong2* ph = reinterpret_cast<const ulonglong2*>(hsf);
#pragma unroll 4
    for (int k4 = 0; k4 < Hdim/4; k4++) {
        F4U w0, w1, w2;
        w0.f = pw[k4*128]; w1.f = pw[k4*128+4096]; w2.f = pw[k4*128+8192];
        ulonglong2 h[RB];
#pragma unroll
        for (int i = 0; i < RB; i++) h[i] = ph[i*32 + k4];
#pragma unroll
        for (int i = 0; i < RB; i++) {
            ffma2(ar[i],h[i].x,w0.u.x); ffma2(az[i],h[i].x,w1.u.x); ffma2(anh[i],h[i].x,w2.u.x);
            ffma2(ar[i],h[i].y,w0.u.y); ffma2(az[i],h[i].y,w1.u.y); ffma2(anh[i],h[i].y,w2.u.y);
        }
    }
    const float4* pwi = reinterpret_cast<const float4*>(wiP) + j;
    const ulonglong2* pp = reinterpret_cast<const ulonglong2*>(psf);
#pragma unroll
    for (int k4 = 0; k4 < Odim/4; k4++) {
        F4U w0, w1, w2;
        w0.f = pwi[k4*128]; w1.f = pwi[k4*128+1024]; w2.f = pwi[k4*128+2048];
        ulonglong2 p[RB];
#pragma unroll
        for (int i = 0; i < RB; i++) p[i] = pp[i*8 + k4];
#pragma unroll
        for (int i = 0; i < RB; i++) {
            ffma2(ar[i],p[i].x,w0.u.x); ffma2(az[i],p[i].x,w1.u.x); ffma2(anx[i],p[i].x,w2.u.x);
            ffma2(ar[i],p[i].y,w0.u.y); ffma2(az[i],p[i].y,w1.u.y); ffma2(anx[i],p[i].y,w2.u.y);
        }
    }
#pragma unroll
    for (int i = 0; i < RB; i++) {
        float rg = sigmoidf_(f2sum(ar[i]));
        float zg = sigmoidf_(f2sum(az[i]));
        float n  = tanhf(f2sum(anx[i]) + rg*f2sum(anh[i]));
        out[i] = (1.0f - zg)*n + zg*hsf[i*Hdim + j];
    }
}

__global__ void __launch_bounds__(NTHR, 4)
combine_kernel(const float* __restrict__ probs_fc,
               const float* __restrict__ h_ai, const float* __restrict__ h_a,
               const float* __restrict__ wiP,  const float* __restrict__ bi,
               const float* __restrict__ whP,  const float* __restrict__ bh,
               const float* __restrict__ ufP,  const float* __restrict__ ufb,
               const float* __restrict__ uaP,  const float* __restrict__ uab,
               float* __restrict__ h2_out) {
    __shared__ float hs[RB * Hdim];
    __shared__ float ps[RB * Odim];
    __shared__ float hf[RB * Hdim];
    const int t = threadIdx.x, row0 = blockIdx.x * RB;
    {
        const float4* src = reinterpret_cast<const float4*>(h_ai + (size_t)row0*Hdim);
        float4* dst = reinterpret_cast<float4*>(hs);
#pragma unroll
        for (int i = t; i < RB*Hdim/4; i += NTHR) dst[i] = src[i];
        const float4* psrc = reinterpret_cast<const float4*>(probs_fc + (size_t)row0*Odim);
        if (t < RB*Odim/4) reinterpret_cast<float4*>(ps)[t] = psrc[t];
    }
    __syncthreads();
    float out[RB];
    gru_rows8(hs, ps, t, whP, wiP, bi, bh, out);
#pragma unroll
    for (int i = 0; i < RB; i++) hf[i*Hdim + t] = out[i];
    __syncthreads();
    {
        const float4* src = reinterpret_cast<const float4*>(h_a + (size_t)row0*Hdim);
        float4* dst = reinterpret_cast<float4*>(hs);
#pragma unroll
        for (int i = t; i < RB*Hdim/4; i += NTHR) dst[i] = src[i];
    }
    __syncthreads();
    const float bb = ufb[t] + uab[t];
    u64 acc[RB];
#pragma unroll
    for (int i = 0; i < RB; i++) acc[i] = pack2(bb, 0.0f);
    const float4* pf = reinterpret_cast<const float4*>(ufP) + t;
    const float4* pa = reinterpret_cast<const float4*>(uaP) + t;
    const ulonglong2* phf = reinterpret_cast<const ulonglong2*>(hf);
    const ulonglong2* phs = reinterpret_cast<const ulonglong2*>(hs);
#pragma unroll 4
    for (int k4 = 0; k4 < Hdim/4; k4++) {
        F4U wf, wa;
        wf.f = pf[k4*128]; wa.f = pa[k4*128];
        ulonglong2 hv[RB], av[RB];
#pragma unroll
        for (int i = 0; i < RB; i++) { hv[i]=phf[i*32+k4]; av[i]=phs[i*32+k4]; }
#pragma unroll
        for (int i = 0; i < RB; i++) {
            ffma2(acc[i],hv[i].x,wf.u.x); ffma2(acc[i],hv[i].y,wf.u.y);
            ffma2(acc[i],av[i].x,wa.u.x); ffma2(acc[i],av[i].y,wa.u.y);
        }
    }
    float* po = h2_out + (size_t)row0*Hdim + t;
#pragma unroll
    for (int i = 0; i < RB; i++) po[i*Hdim] = tanhf(f2sum(acc[i]));
}

// ======== host orchestration ========
struct EmitCtx {
    const float *wpred, *h2o_b, *abi, *abh, *fbi, *fbh, *uab, *ufb;
    const float *fwiP, *fwhP, *ufP, *uaP;
    const unsigned char *WTC;
    float *out, *HAI, *H2, *PR;
    int B, idx;
};

static void emit_node(EmitCtx& P, int lvl, int d, const float* h_in) {
    float* probs = P.PR  + (size_t)lvl * P.B * Odim;
    float* h_ai  = P.HAI + (size_t)lvl * P.B * Hdim;
    node_tc<<<P.B / 32, 256, SMEM_TC>>>(h_in, P.wpred, P.h2o_b, P.WTC, P.abi, P.abh,
                                        P.out + (size_t)P.idx * P.B * Odim, probs, h_ai);
    P.idx++;
    if (d > 0) {
        emit_node(P, lvl + 1, d - 1, h_ai);
        float* h2 = P.H2 + (size_t)lvl * P.B * Hdim;
        combine_kernel<<<P.B / RB, NTHR>>>(P.PR + (size_t)(lvl+1) * P.B * Odim,
                                           h_ai, h_in, P.fwiP, P.fbi, P.fwhP, P.fbh,
                                           P.ufP, P.ufb, P.uaP, P.uab, h2);
        emit_node(P, lvl + 1, d - 1, h2);
    }
}

extern "C" void kernel_launch(void* const* d_in, const int* in_sizes, int n_in,
                              void* d_out, int out_size) {
    const float* z     = (const float*)d_in[0];
    const float* z2h_w = (const float*)d_in[1];
    const float* z2h_b = (const float*)d_in[2];
    const float* h2o_w = (const float*)d_in[3];
    const float* h2o_b = (const float*)d_in[4];
    const float* awi   = (const float*)d_in[5];
    const float* abi   = (const float*)d_in[6];
    const float* awh   = (const float*)d_in[7];
    const float* abh   = (const float*)d_in[8];
    const float* fwi   = (const float*)d_in[9];
    const float* fbi   = (const float*)d_in[10];
    const float* fwh   = (const float*)d_in[11];
    const float* fbh   = (const float*)d_in[12];
    const float* uaw   = (const float*)d_in[13];
    const float* uab   = (const float*)d_in[14];
    const float* ufw   = (const float*)d_in[15];
    const float* ufb   = (const float*)d_in[16];

    const int H  = in_sizes[2];
    const int O  = in_sizes[4];
    const int IN = in_sizes[1] / H;
    const int B  = in_sizes[0] / IN;
    const int nn = out_size / (B * O);
    int depth = 0;
    while (((2 << depth) - 1) < nn) depth++;

    float *H0p, *HAIp, *H2p, *PRp, *WPp, *WPRp;
    unsigned char *WTCp;
    cudaGetSymbolAddress((void**)&H0p,  g_H0);
    cudaGetSymbolAddress((void**)&HAIp, g_HAI);
    cudaGetSymbolAddress((void**)&H2p,  g_H2);
    cudaGetSymbolAddress((void**)&PRp,  g_PR);
    cudaGetSymbolAddress((void**)&WPp,  g_WP);
    cudaGetSymbolAddress((void**)&WPRp, g_WPRED);
    cudaGetSymbolAddress((void**)&WTCp, g_WTC);

    cudaFuncSetAttribute(node_tc, cudaFuncAttributeMaxDynamicSharedMemorySize, SMEM_TC);

    pack_kernel<<<(25600 + 255) / 256, 256>>>(fwh, fwi, ufw, uaw, h2o_w, WPp, WPRp);
    pack_wtc<<<(2560 + 127) / 128, 128>>>(awh, awi, WTCp);
    init_kernel<<<B / RB, NTHR>>>(z, z2h_w, z2h_b, H0p);

    EmitCtx P;
    P.wpred = WPRp; P.h2o_b = h2o_b;
    P.abi = abi; P.abh = abh; P.fbi = fbi; P.fbh = fbh;
    P.uab = uab; P.ufb = ufb;
    P.fwiP = WPp + OFF_WI_F; P.fwhP = WPp + OFF_WH_F;
    P.ufP  = WPp + OFF_UF;   P.uaP  = WPp + OFF_UA;
    P.WTC = WTCp;
    P.out = (float*)d_out;
    P.HAI = HAIp; P.H2 = H2p; P.PR = PRp;
    P.B = B; P.idx = 0;

    emit_node(P, 0, depth, H0p);
}

// round 12
// speedup vs baseline: 1.5029x; 1.5029x over previous
#include <cuda_runtime.h>
#include <cuda_fp16.h>
#include <cstdint>

#define Hdim 128
#define Odim 32
#define INdim 64
#define RB 8
#define NTHR 128
#define MAXB 16384
#define MAXLVL 6

__device__ float g_H0 [(size_t)MAXB * Hdim];
__device__ float g_HAI[(size_t)MAXLVL * MAXB * Hdim];
__device__ float g_H2 [(size_t)MAXLVL * MAXB * Hdim];
__device__ float g_PR [(size_t)(MAXLVL + 1) * MAXB * Odim];

#define OFF_WH_F 0
#define OFF_WI_F 49152
#define OFF_UF   61440
#define OFF_UA   77824
__device__ float g_WP[94208];
__device__ float g_WPRED[4096];
__device__ __align__(1024) unsigned char g_WTC[163840]; // [5 chunk][512 n][64B] fp16 swizzled

typedef unsigned long long u64;
union F4U { float4 f; ulonglong2 u; };

__device__ __forceinline__ void ffma2(u64& d, u64 a, u64 b) {
    asm volatile("fma.rn.f32x2 %0, %1, %2, %0;" : "+l"(d) : "l"(a), "l"(b));
}
__device__ __forceinline__ u64 pack2(float lo, float hi) {
    u64 r; asm("mov.b64 %0, {%1, %2};" : "=l"(r) : "f"(lo), "f"(hi)); return r;
}
__device__ __forceinline__ float f2sum(u64 v) {
    float lo, hi; asm("mov.b64 {%0, %1}, %2;" : "=f"(lo), "=f"(hi) : "l"(v));
    return lo + hi;
}
__device__ __forceinline__ float sigmoidf_(float x) { return 1.0f / (1.0f + expf(-x)); }
__device__ __forceinline__ uint32_t smem_u32(const void* p) {
    uint32_t a;
    asm("{ .reg .u64 t; cvta.to.shared.u64 t, %1; cvt.u32.u64 %0, t; }" : "=r"(a) : "l"(p));
    return a;
}
__device__ __forceinline__ void ldsm4(uint32_t* r, uint32_t a) {
    asm volatile("ldmatrix.sync.aligned.m8n8.x4.shared.b16 {%0,%1,%2,%3}, [%4];"
        : "=r"(r[0]),"=r"(r[1]),"=r"(r[2]),"=r"(r[3]) : "r"(a));
}
__device__ __forceinline__ void mma16816(float* c, const uint32_t* a, const uint32_t* b) {
    asm volatile("mma.sync.aligned.m16n8k16.row.col.f32.f16.f16.f32 "
        "{%0,%1,%2,%3}, {%4,%5,%6,%7}, {%8,%9}, {%0,%1,%2,%3};"
        : "+f"(c[0]),"+f"(c[1]),"+f"(c[2]),"+f"(c[3])
        : "r"(a[0]),"r"(a[1]),"r"(a[2]),"r"(a[3]),"r"(b[0]),"r"(b[1]));
}
#define CPA16(d, s) asm volatile("cp.async.cg.shared.global [%0], [%1], 16;" :: "r"(d), "l"(s))
#define CPCOMMIT()  asm volatile("cp.async.commit_group;")
#define CPWAIT1()   asm volatile("cp.async.wait_group 1;")
#define CPWAIT0()   asm volatile("cp.async.wait_group 0;")

__device__ __forceinline__ void pack_one(const float* __restrict__ s, float* __restrict__ d, int g) {
    int k4 = g >> 7, j = g & 127;
    float4 v;
    v.x = s[(size_t)(4*k4+0)*128+j]; v.y = s[(size_t)(4*k4+1)*128+j];
    v.z = s[(size_t)(4*k4+2)*128+j]; v.w = s[(size_t)(4*k4+3)*128+j];
    *reinterpret_cast<float4*>(d + (size_t)g*4) = v;
}
__global__ void pack_kernel(const float* __restrict__ fwh, const float* __restrict__ fwi,
                            const float* __restrict__ ufw, const float* __restrict__ uaw,
                            const float* __restrict__ h2o_w,
                            float* __restrict__ WP, float* __restrict__ WPRED) {
    int g = blockIdx.x * blockDim.x + threadIdx.x;
    if      (g < 12288) pack_one(fwh, WP + OFF_WH_F, g);
    else if (g < 15360) pack_one(fwi, WP + OFF_WI_F, g - 12288);
    else if (g < 19456) pack_one(ufw, WP + OFF_UF,   g - 15360);
    else if (g < 23552) pack_one(uaw, WP + OFF_UA,   g - 19456);
    else if (g < 25600) {
        int g2 = g - 23552, k2 = g2 >> 5, o = g2 & 31;
        WPRED[g2*2]   = h2o_w[(size_t)(2*k2)*32+o];
        WPRED[g2*2+1] = h2o_w[(size_t)(2*k2+1)*32+o];
    }
}
// fp16 single-plane B, seg-swizzled: seg s of row n at n*64 + ((s+(n>>1))&3)*16
__global__ void pack_wtc(const float* __restrict__ awh, const float* __restrict__ awi,
                         unsigned char* __restrict__ WTC) {
    int id = blockIdx.x * blockDim.x + threadIdx.x;
    if (id >= 2560) return;
    int c = id / 512, n = id % 512;
    int gate = n >> 7, j = n & 127;
    for (int s = 0; s < 4; s++) {
        __half seg[8];
        for (int i = 0; i < 8; i++) {
            int gk = c*32 + s*8 + i;
            float w;
            if      (gate == 0) w = gk < 128 ? awh[(size_t)gk*128 + j] : awi[(size_t)(gk-128)*128 + j];
            else if (gate == 1) w = gk < 128 ? awh[16384 + (size_t)gk*128 + j] : awi[4096 + (size_t)(gk-128)*128 + j];
            else if (gate == 2) w = gk < 128 ? awh[32768 + (size_t)gk*128 + j] : 0.0f;
            else                w = gk < 128 ? 0.0f : awi[8192 + (size_t)(gk-128)*128 + j];
            seg[i] = __float2half_rn(w);
        }
        size_t off = (size_t)c*32768 + (size_t)n*64 + (size_t)((s + (n>>1)) & 3)*16;
        *(float4*)(WTC + off) = *(const float4*)seg;
    }
}

__global__ void __launch_bounds__(NTHR)
init_kernel(const float* __restrict__ z, const float* __restrict__ w,
            const float* __restrict__ b, float* __restrict__ hout) {
    __shared__ float zs[RB][INdim];
    const int j = threadIdx.x, row0 = blockIdx.x * RB;
    {
        const float4* src = reinterpret_cast<const float4*>(z + (size_t)row0 * INdim);
        float4* dst = reinterpret_cast<float4*>(&zs[0][0]);
        for (int i = j; i < RB * INdim / 4; i += NTHR) dst[i] = src[i];
    }
    __syncthreads();
    const float bb = b[j];
    float acc[RB];
#pragma unroll
    for (int i = 0; i < RB; i++) acc[i] = bb;
#pragma unroll 4
    for (int k = 0; k < INdim; k += 4) {
        float4 hv[RB];
#pragma unroll
        for (int i = 0; i < RB; i++) hv[i] = *reinterpret_cast<const float4*>(&zs[i][k]);
#pragma unroll
        for (int kk = 0; kk < 4; kk++) {
            float wv = w[(size_t)(k+kk)*Hdim + j];
#pragma unroll
            for (int i = 0; i < RB; i++) {
                float h = (kk==0)?hv[i].x:(kk==1)?hv[i].y:(kk==2)?hv[i].z:hv[i].w;
                acc[i] += h * wv;
            }
        }
    }
#pragma unroll
    for (int i = 0; i < RB; i++) hout[(size_t)(row0+i)*Hdim + j] = acc[i];
}

// ======== fp16 mma node kernel: M=64, 512 thr, 2m x 8n warps ========
#define SM_AHI  0
#define SM_ALO  21504
#define SM_B    43008
#define SMEM_TC 108544
#define APITCH  336

__global__ void __launch_bounds__(512, 1)
node_tc(const float* __restrict__ h_a,
        const float* __restrict__ wpred, const float* __restrict__ h2o_b,
        const unsigned char* __restrict__ WTC,
        const float* __restrict__ abi, const float* __restrict__ abh,
        float* __restrict__ pred_out, float* __restrict__ probs_out,
        float* __restrict__ h_out) {
    extern __shared__ __align__(128) unsigned char smem[];
    const uint32_t sb = smem_u32(smem);
    const int t = threadIdx.x, wid = t >> 5, lane = t & 31;
    const int row0 = blockIdx.x * 64;

    for (int i = t; i < 2048; i += 512) {  // h -> A hi/lo fp16, cols 0-127
        int row = i >> 5, k4 = i & 31;
        float4 v = ((const float4*)(h_a + (size_t)(row0+row)*Hdim))[k4];
        __half2 h01 = __floats2half2_rn(v.x, v.y);
        __half2 h23 = __floats2half2_rn(v.z, v.w);
        __half2 l01 = __floats2half2_rn(v.x - __half2float(h01.x), v.y - __half2float(h01.y));
        __half2 l23 = __floats2half2_rn(v.z - __half2float(h23.x), v.w - __half2float(h23.y));
        uint32_t o = (uint32_t)row*APITCH + k4*8;
        *(__half2*)(smem + SM_AHI + o)     = h01;
        *(__half2*)(smem + SM_AHI + o + 4) = h23;
        *(__half2*)(smem + SM_ALO + o)     = l01;
        *(__half2*)(smem + SM_ALO + o + 4) = l23;
    }
    {   // chunk 0 prefetch
        uint32_t dst = sb + SM_B + (uint32_t)t*64u;
        const unsigned char* s0 = WTC + (size_t)t*64;
#pragma unroll
        for (int q = 0; q < 4; q++) CPA16(dst + q*16, s0 + q*16);
        CPCOMMIT();
    }
    {   // pred fp32 + softmax; probs -> A cols 128-159
        const float bo = h2o_b[lane];
        const u64* WPp = (const u64*)wpred;
        for (int rr = 0; rr < 4; rr++) {
            int row = wid*4 + rr, grow = row0 + row;
            const u64* hr = (const u64*)(h_a + (size_t)grow*Hdim);
            u64 acc = pack2(bo, 0.0f);
#pragma unroll 8
            for (int k2 = 0; k2 < 64; k2++) ffma2(acc, hr[k2], WPp[k2*32 + lane]);
            float v = f2sum(acc), m = v;
#pragma unroll
            for (int s = 16; s > 0; s >>= 1) m = fmaxf(m, __shfl_xor_sync(~0u, m, s));
            float e = expf(v - m), ss = e;
#pragma unroll
            for (int s = 16; s > 0; s >>= 1) ss += __shfl_xor_sync(~0u, ss, s);
            float p = e / ss;
            pred_out[(size_t)grow*Odim + lane]  = v;
            probs_out[(size_t)grow*Odim + lane] = p;
            __half ph = __float2half_rn(p);
            __half pl = __float2half_rn(p - __half2float(ph));
            uint32_t o = (uint32_t)row*APITCH + 256 + 2*lane;
            *(__half*)(smem + SM_AHI + o) = ph;
            *(__half*)(smem + SM_ALO + o) = pl;
        }
    }

    const int wm = wid & 1, wn = wid >> 1;
    float acc[2][8][4];
#pragma unroll
    for (int a = 0; a < 2; a++)
#pragma unroll
        for (int i = 0; i < 8; i++)
#pragma unroll
            for (int q = 0; q < 4; q++) acc[a][i][q] = 0.0f;

    const uint32_t abase = sb + SM_AHI + (uint32_t)(wm*32 + (lane & 15))*APITCH + (uint32_t)(lane >> 4)*16;
    const int roffB = ((lane >> 4) << 3) + (lane & 7);   // g>>1 tile select + row
    const int sgB   = (lane >> 3) & 1;

    for (int c = 0; c < 5; c++) {
        if (c < 4) {
            uint32_t dst = sb + SM_B + (uint32_t)(((c+1)&1))*32768u + (uint32_t)t*64u;
            const unsigned char* s0 = WTC + (size_t)(c+1)*32768 + (size_t)t*64;
#pragma unroll
            for (int q = 0; q < 4; q++) CPA16(dst + q*16, s0 + q*16);
            CPCOMMIT(); CPWAIT1();
        } else CPWAIT0();
        __syncthreads();
        uint32_t bbuf = sb + SM_B + (uint32_t)(c & 1)*32768u;
#pragma unroll
        for (int kk = 0; kk < 2; kk++) {
            uint32_t ah[2][4], al[2][4];
#pragma unroll
            for (int tm = 0; tm < 2; tm++) {
                ldsm4(ah[tm], abase + (uint32_t)tm*16u*APITCH + (uint32_t)(c*32 + kk*16)*2);
                ldsm4(al[tm], abase + 21504u + (uint32_t)tm*16u*APITCH + (uint32_t)(c*32 + kk*16)*2);
            }
#pragma unroll
            for (int tn2 = 0; tn2 < 4; tn2++) {
                int n = wn*64 + tn2*16 + roffB;
                uint32_t ba = bbuf + (uint32_t)n*64u + (uint32_t)(((2*kk + sgB + (n>>1)) & 3))*16u;
                uint32_t b[4];
                ldsm4(b, ba);
#pragma unroll
                for (int tm = 0; tm < 2; tm++) {
                    mma16816(acc[tm][tn2*2],   ah[tm], b);
                    mma16816(acc[tm][tn2*2+1], ah[tm], b+2);
                    mma16816(acc[tm][tn2*2],   al[tm], b);
                    mma16816(acc[tm][tn2*2+1], al[tm], b+2);
                }
            }
        }
        __syncthreads();
    }

    // epilogue: 2-pass gate exchange, 64 rows x 132-pitch x 2 gates
    float* exch = (float*)smem;
    const int row = t >> 3, j0 = (t & 7)*16;
    float rg[16], zg[16];

    if (wn < 4) {           // gates r (wn 0-1), z (wn 2-3)
        int gsel = wn >> 1;
#pragma unroll
        for (int tm = 0; tm < 2; tm++)
#pragma unroll
            for (int tn = 0; tn < 8; tn++) {
                int col = (wn & 1)*64 + tn*8 + 2*(lane & 3);
                int r1 = wm*32 + tm*16 + (lane >> 2);
                *(float2*)&exch[gsel*8448 + r1*132 + col]     = make_float2(acc[tm][tn][0], acc[tm][tn][1]);
                *(float2*)&exch[gsel*8448 + (r1+8)*132 + col] = make_float2(acc[tm][tn][2], acc[tm][tn][3]);
            }
    }
    __syncthreads();
#pragma unroll
    for (int b = 0; b < 4; b++) {
        int j = j0 + b*4;
        float4 vr = *(const float4*)&exch[row*132 + j];
        float4 vz = *(const float4*)&exch[8448 + row*132 + j];
        float4 bir = *(const float4*)&abi[j],     bhr = *(const float4*)&abh[j];
        float4 biz = *(const float4*)&abi[128+j], bhz = *(const float4*)&abh[128+j];
        const float *pr = (const float*)&vr, *pz = (const float*)&vz;
        const float *b1 = (const float*)&bir, *b2 = (const float*)&bhr;
        const float *b3 = (const float*)&biz, *b4 = (const float*)&bhz;
#pragma unroll
        for (int e = 0; e < 4; e++) {
            rg[b*4+e] = sigmoidf_(pr[e] + b1[e] + b2[e]);
            zg[b*4+e] = sigmoidf_(pz[e] + b3[e] + b4[e]);
        }
    }
    __syncthreads();
    if (wn >= 4) {          // gates nh (wn 4-5), nx (wn 6-7)
        int gsel = (wn - 4) >> 1;
#pragma unroll
        for (int tm = 0; tm < 2; tm++)
#pragma unroll
            for (int tn = 0; tn < 8; tn++) {
                int col = (wn & 1)*64 + tn*8 + 2*(lane & 3);
                int r1 = wm*32 + tm*16 + (lane >> 2);
                *(float2*)&exch[gsel*8448 + r1*132 + col]     = make_float2(acc[tm][tn][0], acc[tm][tn][1]);
                *(float2*)&exch[gsel*8448 + (r1+8)*132 + col] = make_float2(acc[tm][tn][2], acc[tm][tn][3]);
            }
    }
    __syncthreads();
#pragma unroll
    for (int b = 0; b < 4; b++) {
        int j = j0 + b*4;
        float4 vh = *(const float4*)&exch[row*132 + j];
        float4 vx = *(const float4*)&exch[8448 + row*132 + j];
        float4 bin = *(const float4*)&abi[256+j], bhn = *(const float4*)&abh[256+j];
        float4 hv = *(const float4*)(h_a + (size_t)(row0+row)*Hdim + j);
        float4 out;
        const float *ph = (const float*)&vh, *px = (const float*)&vx;
        const float *bn = (const float*)&bin, *hn = (const float*)&bhn;
        const float *pv = (const float*)&hv;
        float* po = (float*)&out;
#pragma unroll
        for (int e = 0; e < 4; e++) {
            float nn = tanhf(px[e] + bn[e] + rg[b*4+e]*(ph[e] + hn[e]));
            po[e] = (1.0f - zg[b*4+e])*nn + zg[b*4+e]*pv[e];
        }
        *(float4*)(h_out + (size_t)(row0+row)*Hdim + j) = out;
    }
}

// ======== combine kernel (R5 FFMA2, proven) ========
__device__ __forceinline__ void gru_rows8(
    const float* __restrict__ hsf, const float* __restrict__ psf, int j,
    const float* __restrict__ whP, const float* __restrict__ wiP,
    const float* __restrict__ bi,  const float* __restrict__ bh, float out[RB]) {
    const float br_ = bi[j] + bh[j];
    const float bz_ = bi[128+j] + bh[128+j];
    const float bxn = bi[256+j];
    const float bhn = bh[256+j];
    u64 ar[RB], az[RB], anh[RB], anx[RB];
#pragma unroll
    for (int i = 0; i < RB; i++) {
        ar[i]=pack2(br_,0.f); az[i]=pack2(bz_,0.f); anh[i]=pack2(bhn,0.f); anx[i]=pack2(bxn,0.f);
    }
    const float4* pw = reinterpret_cast<const float4*>(whP) + j;
    const ulonglong2* ph = reinterpret_cast<const ulonglong2*>(hsf);
#pragma unroll 4
    for (int k4 = 0; k4 < Hdim/4; k4++) {
        F4U w0, w1, w2;
        w0.f = pw[k4*128]; w1.f = pw[k4*128+4096]; w2.f = pw[k4*128+8192];
        ulonglong2 h[RB];
#pragma unroll
        for (int i = 0; i < RB; i++) h[i] = ph[i*32 + k4];
#pragma unroll
        for (int i = 0; i < RB; i++) {
            ffma2(ar[i],h[i].x,w0.u.x); ffma2(az[i],h[i].x,w1.u.x); ffma2(anh[i],h[i].x,w2.u.x);
            ffma2(ar[i],h[i].y,w0.u.y); ffma2(az[i],h[i].y,w1.u.y); ffma2(anh[i],h[i].y,w2.u.y);
        }
    }
    const float4* pwi = reinterpret_cast<const float4*>(wiP) + j;
    const ulonglong2* pp = reinterpret_cast<const ulonglong2*>(psf);
#pragma unroll
    for (int k4 = 0; k4 < Odim/4; k4++) {
        F4U w0, w1, w2;
        w0.f = pwi[k4*128]; w1.f = pwi[k4*128+1024]; w2.f = pwi[k4*128+2048];
        ulonglong2 p[RB];
#pragma unroll
        for (int i = 0; i < RB; i++) p[i] = pp[i*8 + k4];
#pragma unroll
        for (int i = 0; i < RB; i++) {
            ffma2(ar[i],p[i].x,w0.u.x); ffma2(az[i],p[i].x,w1.u.x); ffma2(anx[i],p[i].x,w2.u.x);
            ffma2(ar[i],p[i].y,w0.u.y); ffma2(az[i],p[i].y,w1.u.y); ffma2(anx[i],p[i].y,w2.u.y);
        }
    }
#pragma unroll
    for (int i = 0; i < RB; i++) {
        float rg = sigmoidf_(f2sum(ar[i]));
        float zg = sigmoidf_(f2sum(az[i]));
        float n  = tanhf(f2sum(anx[i]) + rg*f2sum(anh[i]));
        out[i] = (1.0f - zg)*n + zg*hsf[i*Hdim + j];
    }
}

__global__ void __launch_bounds__(NTHR, 4)
combine_kernel(const float* __restrict__ probs_fc,
               const float* __restrict__ h_ai, const float* __restrict__ h_a,
               const float* __restrict__ wiP,  const float* __restrict__ bi,
               const float* __restrict__ whP,  const float* __restrict__ bh,
               const float* __restrict__ ufP,  const float* __restrict__ ufb,
               const float* __restrict__ uaP,  const float* __restrict__ uab,
               float* __restrict__ h2_out) {
    __shared__ float hs[RB * Hdim];
    __shared__ float ps[RB * Odim];
    __shared__ float hf[RB * Hdim];
    const int t = threadIdx.x, row0 = blockIdx.x * RB;
    {
        const float4* src = reinterpret_cast<const float4*>(h_ai + (size_t)row0*Hdim);
        float4* dst = reinterpret_cast<float4*>(hs);
#pragma unroll
        for (int i = t; i < RB*Hdim/4; i += NTHR) dst[i] = src[i];
        const float4* psrc = reinterpret_cast<const float4*>(probs_fc + (size_t)row0*Odim);
        if (t < RB*Odim/4) reinterpret_cast<float4*>(ps)[t] = psrc[t];
    }
    __syncthreads();
    float out[RB];
    gru_rows8(hs, ps, t, whP, wiP, bi, bh, out);
#pragma unroll
    for (int i = 0; i < RB; i++) hf[i*Hdim + t] = out[i];
    __syncthreads();
    {
        const float4* src = reinterpret_cast<const float4*>(h_a + (size_t)row0*Hdim);
        float4* dst = reinterpret_cast<float4*>(hs);
#pragma unroll
        for (int i = t; i < RB*Hdim/4; i += NTHR) dst[i] = src[i];
    }
    __syncthreads();
    const float bb = ufb[t] + uab[t];
    u64 acc[RB];
#pragma unroll
    for (int i = 0; i < RB; i++) acc[i] = pack2(bb, 0.0f);
    const float4* pf = reinterpret_cast<const float4*>(ufP) + t;
    const float4* pa = reinterpret_cast<const float4*>(uaP) + t;
    const ulonglong2* phf = reinterpret_cast<const ulonglong2*>(hf);
    const ulonglong2* phs = reinterpret_cast<const ulonglong2*>(hs);
#pragma unroll 4
    for (int k4 = 0; k4 < Hdim/4; k4++) {
        F4U wf, wa;
        wf.f = pf[k4*128]; wa.f = pa[k4*128];
        ulonglong2 hv[RB], av[RB];
#pragma unroll
        for (int i = 0; i < RB; i++) { hv[i]=phf[i*32+k4]; av[i]=phs[i*32+k4]; }
#pragma unroll
        for (int i = 0; i < RB; i++) {
            ffma2(acc[i],hv[i].x,wf.u.x); ffma2(acc[i],hv[i].y,wf.u.y);
            ffma2(acc[i],av[i].x,wa.u.x); ffma2(acc[i],av[i].y,wa.u.y);
        }
    }
    float* po = h2_out + (size_t)row0*Hdim + t;
#pragma unroll
    for (int i = 0; i < RB; i++) po[i*Hdim] = tanhf(f2sum(acc[i]));
}

// ======== host orchestration ========
struct EmitCtx {
    const float *wpred, *h2o_b, *abi, *abh, *fbi, *fbh, *uab, *ufb;
    const float *fwiP, *fwhP, *ufP, *uaP;
    const unsigned char *WTC;
    float *out, *HAI, *H2, *PR;
    int B, idx;
};

static void emit_node(EmitCtx& P, int lvl, int d, const float* h_in) {
    float* probs = P.PR  + (size_t)lvl * P.B * Odim;
    float* h_ai  = P.HAI + (size_t)lvl * P.B * Hdim;
    node_tc<<<P.B / 64, 512, SMEM_TC>>>(h_in, P.wpred, P.h2o_b, P.WTC, P.abi, P.abh,
                                        P.out + (size_t)P.idx * P.B * Odim, probs, h_ai);
    P.idx++;
    if (d > 0) {
        emit_node(P, lvl + 1, d - 1, h_ai);
        float* h2 = P.H2 + (size_t)lvl * P.B * Hdim;
        combine_kernel<<<P.B / RB, NTHR>>>(P.PR + (size_t)(lvl+1) * P.B * Odim,
                                           h_ai, h_in, P.fwiP, P.fbi, P.fwhP, P.fbh,
                                           P.ufP, P.ufb, P.uaP, P.uab, h2);
        emit_node(P, lvl + 1, d - 1, h2);
    }
}

extern "C" void kernel_launch(void* const* d_in, const int* in_sizes, int n_in,
                              void* d_out, int out_size) {
    const float* z     = (const float*)d_in[0];
    const float* z2h_w = (const float*)d_in[1];
    const float* z2h_b = (const float*)d_in[2];
    const float* h2o_w = (const float*)d_in[3];
    const float* h2o_b = (const float*)d_in[4];
    const float* awi   = (const float*)d_in[5];
    const float* abi   = (const float*)d_in[6];
    const float* awh   = (const float*)d_in[7];
    const float* abh   = (const float*)d_in[8];
    const float* fwi   = (const float*)d_in[9];
    const float* fbi   = (const float*)d_in[10];
    const float* fwh   = (const float*)d_in[11];
    const float* fbh   = (const float*)d_in[12];
    const float* uaw   = (const float*)d_in[13];
    const float* uab   = (const float*)d_in[14];
    const float* ufw   = (const float*)d_in[15];
    const float* ufb   = (const float*)d_in[16];

    const int H  = in_sizes[2];
    const int O  = in_sizes[4];
    const int IN = in_sizes[1] / H;
    const int B  = in_sizes[0] / IN;
    const int nn = out_size / (B * O);
    int depth = 0;
    while (((2 << depth) - 1) < nn) depth++;

    float *H0p, *HAIp, *H2p, *PRp, *WPp, *WPRp;
    unsigned char *WTCp;
    cudaGetSymbolAddress((void**)&H0p,  g_H0);
    cudaGetSymbolAddress((void**)&HAIp, g_HAI);
    cudaGetSymbolAddress((void**)&H2p,  g_H2);
    cudaGetSymbolAddress((void**)&PRp,  g_PR);
    cudaGetSymbolAddress((void**)&WPp,  g_WP);
    cudaGetSymbolAddress((void**)&WPRp, g_WPRED);
    cudaGetSymbolAddress((void**)&WTCp, g_WTC);

    cudaFuncSetAttribute(node_tc, cudaFuncAttributeMaxDynamicSharedMemorySize, SMEM_TC);

    pack_kernel<<<(25600 + 255) / 256, 256>>>(fwh, fwi, ufw, uaw, h2o_w, WPp, WPRp);
    pack_wtc<<<(2560 + 127) / 128, 128>>>(awh, awi, WTCp);
    init_kernel<<<B / RB, NTHR>>>(z, z2h_w, z2h_b, H0p);

    EmitCtx P;
    P.wpred = WPRp; P.h2o_b = h2o_b;
    P.abi = abi; P.abh = abh; P.fbi = fbi; P.fbh = fbh;
    P.uab = uab; P.ufb = ufb;
    P.fwiP = WPp + OFF_WI_F; P.fwhP = WPp + OFF_WH_F;
    P.ufP  = WPp + OFF_UF;   P.uaP  = WPp + OFF_UA;
    P.WTC = WTCp;
    P.out = (float*)d_out;
    P.HAI = HAIp; P.H2 = H2p; P.PR = PRp;
    P.B = B; P.idx = 0;

    emit_node(P, 0, depth, H0p);
}

// round 13
// speedup vs baseline: 1.7125x; 1.1394x over previous
#include <cuda_runtime.h>
#include <cuda_fp16.h>
#include <cstdint>

#define Hdim 128
#define Odim 32
#define INdim 64
#define RB 8
#define NTHR 128
#define MAXB 16384
#define MAXLVL 6

__device__ float g_H0 [(size_t)MAXB * Hdim];
__device__ float g_HAI[(size_t)MAXLVL * MAXB * Hdim];
__device__ float g_H2 [(size_t)MAXLVL * MAXB * Hdim];
__device__ float g_PR [(size_t)(MAXLVL + 1) * MAXB * Odim];

__device__ float g_WPRED[4096];
__device__ __align__(1024) unsigned char g_WTC [163840]; // gru_a  [5][512n][64B]
__device__ __align__(1024) unsigned char g_WTCF[163840]; // gru_f  [5][512n][64B]
__device__ __align__(1024) unsigned char g_WU  [65536];  // uf;ua  [8][128n][64B]

typedef unsigned long long u64;

__device__ __forceinline__ void ffma2(u64& d, u64 a, u64 b) {
    asm volatile("fma.rn.f32x2 %0, %1, %2, %0;" : "+l"(d) : "l"(a), "l"(b));
}
__device__ __forceinline__ u64 pack2(float lo, float hi) {
    u64 r; asm("mov.b64 %0, {%1, %2};" : "=l"(r) : "f"(lo), "f"(hi)); return r;
}
__device__ __forceinline__ float f2sum(u64 v) {
    float lo, hi; asm("mov.b64 {%0, %1}, %2;" : "=f"(lo), "=f"(hi) : "l"(v));
    return lo + hi;
}
__device__ __forceinline__ float sigmoidf_(float x) { return 1.0f / (1.0f + expf(-x)); }
__device__ __forceinline__ uint32_t smem_u32(const void* p) {
    uint32_t a;
    asm("{ .reg .u64 t; cvta.to.shared.u64 t, %1; cvt.u32.u64 %0, t; }" : "=r"(a) : "l"(p));
    return a;
}
__device__ __forceinline__ void ldsm4(uint32_t* r, uint32_t a) {
    asm volatile("ldmatrix.sync.aligned.m8n8.x4.shared.b16 {%0,%1,%2,%3}, [%4];"
        : "=r"(r[0]),"=r"(r[1]),"=r"(r[2]),"=r"(r[3]) : "r"(a));
}
__device__ __forceinline__ void mma16816(float* c, const uint32_t* a, const uint32_t* b) {
    asm volatile("mma.sync.aligned.m16n8k16.row.col.f32.f16.f16.f32 "
        "{%0,%1,%2,%3}, {%4,%5,%6,%7}, {%8,%9}, {%0,%1,%2,%3};"
        : "+f"(c[0]),"+f"(c[1]),"+f"(c[2]),"+f"(c[3])
        : "r"(a[0]),"r"(a[1]),"r"(a[2]),"r"(a[3]),"r"(b[0]),"r"(b[1]));
}
#define CPA16(d, s) asm volatile("cp.async.cg.shared.global [%0], [%1], 16;" :: "r"(d), "l"(s))
#define CPCOMMIT()  asm volatile("cp.async.commit_group;")
#define CPWAIT1()   asm volatile("cp.async.wait_group 1;")
#define CPWAIT0()   asm volatile("cp.async.wait_group 0;")

__global__ void pack_pred(const float* __restrict__ h2o_w, float* __restrict__ WPRED) {
    int g2 = blockIdx.x * blockDim.x + threadIdx.x;
    if (g2 >= 2048) return;
    int k2 = g2 >> 5, o = g2 & 31;
    WPRED[g2*2]   = h2o_w[(size_t)(2*k2)*32+o];
    WPRED[g2*2+1] = h2o_w[(size_t)(2*k2+1)*32+o];
}
// fp16 B packs, seg-swizzled: seg s of row n at n*64 + ((s+(n>>1))&3)*16
__device__ __forceinline__ void pack_gate(const float* wh, const float* wi, unsigned char* W,
                                          int c, int n) {
    int gate = n >> 7, j = n & 127;
    for (int s = 0; s < 4; s++) {
        __half seg[8];
        for (int i = 0; i < 8; i++) {
            int gk = c*32 + s*8 + i;
            float w;
            if      (gate == 0) w = gk < 128 ? wh[(size_t)gk*128 + j] : wi[(size_t)(gk-128)*128 + j];
            else if (gate == 1) w = gk < 128 ? wh[16384 + (size_t)gk*128 + j] : wi[4096 + (size_t)(gk-128)*128 + j];
            else if (gate == 2) w = gk < 128 ? wh[32768 + (size_t)gk*128 + j] : 0.0f;
            else                w = gk < 128 ? 0.0f : wi[8192 + (size_t)(gk-128)*128 + j];
            seg[i] = __float2half_rn(w);
        }
        size_t off = (size_t)c*32768 + (size_t)n*64 + (size_t)((s + (n>>1)) & 3)*16;
        *(float4*)(W + off) = *(const float4*)seg;
    }
}
__global__ void pack_wtc(const float* __restrict__ awh, const float* __restrict__ awi,
                         const float* __restrict__ fwh, const float* __restrict__ fwi,
                         const float* __restrict__ ufw, const float* __restrict__ uaw,
                         unsigned char* __restrict__ WTC, unsigned char* __restrict__ WTCF,
                         unsigned char* __restrict__ WU) {
    int id = blockIdx.x * blockDim.x + threadIdx.x;
    if (id < 2560)      pack_gate(awh, awi, WTC,  id / 512, id % 512);
    else if (id < 5120) pack_gate(fwh, fwi, WTCF, (id-2560) / 512, (id-2560) % 512);
    else if (id < 6144) {
        int q = id - 5120, c = q >> 7, n = q & 127;     // c 0..7
        const float* W = (c < 4) ? ufw : uaw;
        int kb = (c & 3) * 32;
        for (int s = 0; s < 4; s++) {
            __half seg[8];
            for (int i = 0; i < 8; i++)
                seg[i] = __float2half_rn(W[(size_t)(kb + s*8 + i)*128 + n]);
            size_t off = (size_t)c*8192 + (size_t)n*64 + (size_t)((s + (n>>1)) & 3)*16;
            *(float4*)(WU + off) = *(const float4*)seg;
        }
    }
}

__global__ void __launch_bounds__(NTHR)
init_kernel(const float* __restrict__ z, const float* __restrict__ w,
            const float* __restrict__ b, float* __restrict__ hout) {
    __shared__ float zs[RB][INdim];
    const int j = threadIdx.x, row0 = blockIdx.x * RB;
    {
        const float4* src = reinterpret_cast<const float4*>(z + (size_t)row0 * INdim);
        float4* dst = reinterpret_cast<float4*>(&zs[0][0]);
        for (int i = j; i < RB * INdim / 4; i += NTHR) dst[i] = src[i];
    }
    __syncthreads();
    const float bb = b[j];
    float acc[RB];
#pragma unroll
    for (int i = 0; i < RB; i++) acc[i] = bb;
#pragma unroll 4
    for (int k = 0; k < INdim; k += 4) {
        float4 hv[RB];
#pragma unroll
        for (int i = 0; i < RB; i++) hv[i] = *reinterpret_cast<const float4*>(&zs[i][k]);
#pragma unroll
        for (int kk = 0; kk < 4; kk++) {
            float wv = w[(size_t)(k+kk)*Hdim + j];
#pragma unroll
            for (int i = 0; i < RB; i++) {
                float h = (kk==0)?hv[i].x:(kk==1)?hv[i].y:(kk==2)?hv[i].z:hv[i].w;
                acc[i] += h * wv;
            }
        }
    }
#pragma unroll
    for (int i = 0; i < RB; i++) hout[(size_t)(row0+i)*Hdim + j] = acc[i];
}

#define SM_AHI  0
#define SM_ALO  21504
#define SM_B    43008
#define SMEM_TC 108544
#define APITCH  336

// shared helpers for the mma kernels
__device__ __forceinline__ void load_h_tiles(unsigned char* smem, const float* __restrict__ h,
                                             int row0, int t) {
    for (int i = t; i < 2048; i += 512) {
        int row = i >> 5, k4 = i & 31;
        float4 v = ((const float4*)(h + (size_t)(row0+row)*Hdim))[k4];
        __half2 h01 = __floats2half2_rn(v.x, v.y);
        __half2 h23 = __floats2half2_rn(v.z, v.w);
        __half2 l01 = __floats2half2_rn(v.x - __half2float(h01.x), v.y - __half2float(h01.y));
        __half2 l23 = __floats2half2_rn(v.z - __half2float(h23.x), v.w - __half2float(h23.y));
        uint32_t o = (uint32_t)row*APITCH + k4*8;
        *(__half2*)(smem + SM_AHI + o)     = h01;
        *(__half2*)(smem + SM_AHI + o + 4) = h23;
        *(__half2*)(smem + SM_ALO + o)     = l01;
        *(__half2*)(smem + SM_ALO + o + 4) = l23;
    }
}
// gate mma loop: 5 chunks from W, acc[2][8][4]
__device__ __forceinline__ void gate_mma(uint32_t sb, unsigned char* smem,
                                         const unsigned char* __restrict__ W,
                                         int t, int wm, int wn, int lane, float acc[2][8][4]) {
    const uint32_t abase = sb + SM_AHI + (uint32_t)(wm*32 + (lane & 15))*APITCH + (uint32_t)(lane >> 4)*16;
    const int roffB = ((lane >> 4) << 3) + (lane & 7);
    const int sgB   = (lane >> 3) & 1;
    for (int c = 0; c < 5; c++) {
        if (c < 4) {
            uint32_t dst = sb + SM_B + (uint32_t)(((c+1)&1))*32768u + (uint32_t)t*64u;
            const unsigned char* s0 = W + (size_t)(c+1)*32768 + (size_t)t*64;
#pragma unroll
            for (int q = 0; q < 4; q++) CPA16(dst + q*16, s0 + q*16);
            CPCOMMIT(); CPWAIT1();
        } else CPWAIT0();
        __syncthreads();
        uint32_t bbuf = sb + SM_B + (uint32_t)(c & 1)*32768u;
#pragma unroll
        for (int kk = 0; kk < 2; kk++) {
            uint32_t ah[2][4], al[2][4];
#pragma unroll
            for (int tm = 0; tm < 2; tm++) {
                ldsm4(ah[tm], abase + (uint32_t)tm*16u*APITCH + (uint32_t)(c*32 + kk*16)*2);
                ldsm4(al[tm], abase + 21504u + (uint32_t)tm*16u*APITCH + (uint32_t)(c*32 + kk*16)*2);
            }
#pragma unroll
            for (int tn2 = 0; tn2 < 4; tn2++) {
                int n = wn*64 + tn2*16 + roffB;
                uint32_t ba = bbuf + (uint32_t)n*64u + (uint32_t)(((2*kk + sgB + (n>>1)) & 3))*16u;
                uint32_t b[4];
                ldsm4(b, ba);
#pragma unroll
                for (int tm = 0; tm < 2; tm++) {
                    mma16816(acc[tm][tn2*2],   ah[tm], b);
                    mma16816(acc[tm][tn2*2+1], ah[tm], b+2);
                    mma16816(acc[tm][tn2*2],   al[tm], b);
                    mma16816(acc[tm][tn2*2+1], al[tm], b+2);
                }
            }
        }
        __syncthreads();
    }
}
// gate exchange + GRU epilogue -> hprime[16] per thread (row t>>3, cols (t&7)*16..)
__device__ __forceinline__ void gate_epilogue(unsigned char* smem, float acc[2][8][4],
                                              const float* __restrict__ habs,
                                              const float* __restrict__ abi, const float* __restrict__ abh,
                                              int row0, int t, int wm, int wn, int lane,
                                              float hprime[16]) {
    float* exch = (float*)smem;
    const int row = t >> 3, j0 = (t & 7)*16;
    float rg[16], zg[16];
    if (wn < 4) {
        int gsel = wn >> 1;
#pragma unroll
        for (int tm = 0; tm < 2; tm++)
#pragma unroll
            for (int tn = 0; tn < 8; tn++) {
                int col = (wn & 1)*64 + tn*8 + 2*(lane & 3);
                int r1 = wm*32 + tm*16 + (lane >> 2);
                *(float2*)&exch[gsel*8448 + r1*132 + col]     = make_float2(acc[tm][tn][0], acc[tm][tn][1]);
                *(float2*)&exch[gsel*8448 + (r1+8)*132 + col] = make_float2(acc[tm][tn][2], acc[tm][tn][3]);
            }
    }
    __syncthreads();
#pragma unroll
    for (int b = 0; b < 4; b++) {
        int j = j0 + b*4;
        float4 vr = *(const float4*)&exch[row*132 + j];
        float4 vz = *(const float4*)&exch[8448 + row*132 + j];
        float4 bir = *(const float4*)&abi[j],     bhr = *(const float4*)&abh[j];
        float4 biz = *(const float4*)&abi[128+j], bhz = *(const float4*)&abh[128+j];
        const float *pr = (const float*)&vr, *pz = (const float*)&vz;
        const float *b1 = (const float*)&bir, *b2 = (const float*)&bhr;
        const float *b3 = (const float*)&biz, *b4 = (const float*)&bhz;
#pragma unroll
        for (int e = 0; e < 4; e++) {
            rg[b*4+e] = sigmoidf_(pr[e] + b1[e] + b2[e]);
            zg[b*4+e] = sigmoidf_(pz[e] + b3[e] + b4[e]);
        }
    }
    __syncthreads();
    if (wn >= 4) {
        int gsel = (wn - 4) >> 1;
#pragma unroll
        for (int tm = 0; tm < 2; tm++)
#pragma unroll
            for (int tn = 0; tn < 8; tn++) {
                int col = (wn & 1)*64 + tn*8 + 2*(lane & 3);
                int r1 = wm*32 + tm*16 + (lane >> 2);
                *(float2*)&exch[gsel*8448 + r1*132 + col]     = make_float2(acc[tm][tn][0], acc[tm][tn][1]);
                *(float2*)&exch[gsel*8448 + (r1+8)*132 + col] = make_float2(acc[tm][tn][2], acc[tm][tn][3]);
            }
    }
    __syncthreads();
#pragma unroll
    for (int b = 0; b < 4; b++) {
        int j = j0 + b*4;
        float4 vh = *(const float4*)&exch[row*132 + j];
        float4 vx = *(const float4*)&exch[8448 + row*132 + j];
        float4 bin = *(const float4*)&abi[256+j], bhn = *(const float4*)&abh[256+j];
        float4 hv = *(const float4*)(habs + (size_t)(row0+row)*Hdim + j);
        const float *ph = (const float*)&vh, *px = (const float*)&vx;
        const float *bn = (const float*)&bin, *hn = (const float*)&bhn;
        const float *pv = (const float*)&hv;
#pragma unroll
        for (int e = 0; e < 4; e++) {
            float nn = tanhf(px[e] + bn[e] + rg[b*4+e]*(ph[e] + hn[e]));
            hprime[b*4+e] = (1.0f - zg[b*4+e])*nn + zg[b*4+e]*pv[e];
        }
    }
}

// ======== node kernel (R12, proven) ========
__global__ void __launch_bounds__(512, 1)
node_tc(const float* __restrict__ h_a,
        const float* __restrict__ wpred, const float* __restrict__ h2o_b,
        const unsigned char* __restrict__ WTC,
        const float* __restrict__ abi, const float* __restrict__ abh,
        float* __restrict__ pred_out, float* __restrict__ probs_out,
        float* __restrict__ h_out) {
    extern __shared__ __align__(128) unsigned char smem[];
    const uint32_t sb = smem_u32(smem);
    const int t = threadIdx.x, wid = t >> 5, lane = t & 31;
    const int row0 = blockIdx.x * 64;

    load_h_tiles(smem, h_a, row0, t);
    {
        uint32_t dst = sb + SM_B + (uint32_t)t*64u;
        const unsigned char* s0 = WTC + (size_t)t*64;
#pragma unroll
        for (int q = 0; q < 4; q++) CPA16(dst + q*16, s0 + q*16);
        CPCOMMIT();
    }
    {
        const float bo = h2o_b[lane];
        const u64* WPp = (const u64*)wpred;
        for (int rr = 0; rr < 4; rr++) {
            int row = wid*4 + rr, grow = row0 + row;
            const u64* hr = (const u64*)(h_a + (size_t)grow*Hdim);
            u64 acc = pack2(bo, 0.0f);
#pragma unroll 8
            for (int k2 = 0; k2 < 64; k2++) ffma2(acc, hr[k2], WPp[k2*32 + lane]);
            float v = f2sum(acc), m = v;
#pragma unroll
            for (int s = 16; s > 0; s >>= 1) m = fmaxf(m, __shfl_xor_sync(~0u, m, s));
            float e = expf(v - m), ss = e;
#pragma unroll
            for (int s = 16; s > 0; s >>= 1) ss += __shfl_xor_sync(~0u, ss, s);
            float p = e / ss;
            pred_out[(size_t)grow*Odim + lane]  = v;
            probs_out[(size_t)grow*Odim + lane] = p;
            __half ph = __float2half_rn(p);
            __half pl = __float2half_rn(p - __half2float(ph));
            uint32_t o = (uint32_t)row*APITCH + 256 + 2*lane;
            *(__half*)(smem + SM_AHI + o) = ph;
            *(__half*)(smem + SM_ALO + o) = pl;
        }
    }
    const int wm = wid & 1, wn = wid >> 1;
    float acc[2][8][4];
#pragma unroll
    for (int a = 0; a < 2; a++)
#pragma unroll
        for (int i = 0; i < 8; i++)
#pragma unroll
            for (int q = 0; q < 4; q++) acc[a][i][q] = 0.0f;
    gate_mma(sb, smem, WTC, t, wm, wn, lane, acc);
    float hp[16];
    gate_epilogue(smem, acc, h_a, abi, abh, row0, t, wm, wn, lane, hp);
    {
        const int row = t >> 3, j0 = (t & 7)*16;
        float* po = h_out + (size_t)(row0+row)*Hdim + j0;
#pragma unroll
        for (int q = 0; q < 4; q++)
            *(float4*)(po + q*4) = make_float4(hp[q*4], hp[q*4+1], hp[q*4+2], hp[q*4+3]);
    }
}

// ======== combine kernel (HMMA gates + HMMA merge) ========
__global__ void __launch_bounds__(512, 1)
combine_tc(const float* __restrict__ probs_fc,
           const float* __restrict__ h_ai, const float* __restrict__ h_a,
           const unsigned char* __restrict__ WTCF,
           const float* __restrict__ fbi, const float* __restrict__ fbh,
           const unsigned char* __restrict__ WU,
           const float* __restrict__ ufb, const float* __restrict__ uab,
           float* __restrict__ h2_out) {
    extern __shared__ __align__(128) unsigned char smem[];
    const uint32_t sb = smem_u32(smem);
    const int t = threadIdx.x, lane = t & 31, wid = t >> 5;
    const int wm = wid & 1, wn = wid >> 1;
    const int row0 = blockIdx.x * 64;

    load_h_tiles(smem, h_ai, row0, t);
    {
        uint32_t dst = sb + SM_B + (uint32_t)t*64u;
        const unsigned char* s0 = WTCF + (size_t)t*64;
#pragma unroll
        for (int q = 0; q < 4; q++) CPA16(dst + q*16, s0 + q*16);
        CPCOMMIT();
    }
    for (int i = t*4; i < 2048; i += 2048) {   // probs -> A cols 128-159 (4 per thread)
#pragma unroll
        for (int q = 0; q < 4; q++) {
            int idx = i + q, row = idx >> 5, c = idx & 31;
            float p = probs_fc[(size_t)(row0+row)*Odim + c];
            __half ph = __float2half_rn(p);
            __half pl = __float2half_rn(p - __half2float(ph));
            uint32_t o = (uint32_t)row*APITCH + 256 + 2*c;
            *(__half*)(smem + SM_AHI + o) = ph;
            *(__half*)(smem + SM_ALO + o) = pl;
        }
    }
    __syncthreads();

    float acc[2][8][4];
#pragma unroll
    for (int a = 0; a < 2; a++)
#pragma unroll
        for (int i = 0; i < 8; i++)
#pragma unroll
            for (int q = 0; q < 4; q++) acc[a][i][q] = 0.0f;
    gate_mma(sb, smem, WTCF, t, wm, wn, lane, acc);
    float hf[16];
    gate_epilogue(smem, acc, h_ai, fbi, fbh, row0, t, wm, wn, lane, hf);
    __syncthreads();

    // write hf into A tiles (cols 0-127)
    {
        const int row = t >> 3, j0 = (t & 7)*16;
#pragma unroll
        for (int q = 0; q < 8; q++) {
            float a0 = hf[q*2], a1 = hf[q*2+1];
            __half2 hh = __floats2half2_rn(a0, a1);
            __half2 ll = __floats2half2_rn(a0 - __half2float(hh.x), a1 - __half2float(hh.y));
            uint32_t o = (uint32_t)row*APITCH + (j0 + q*2)*2;
            *(__half2*)(smem + SM_AHI + o) = hh;
            *(__half2*)(smem + SM_ALO + o) = ll;
        }
    }
    __syncthreads();

    // merge: acc2 += A(hf)@uf then A(h_a)@ua; merge B buffers at SM_B (8KB x2)
    float acc2[2][2][4];
#pragma unroll
    for (int a = 0; a < 2; a++)
#pragma unroll
        for (int i = 0; i < 2; i++)
#pragma unroll
            for (int q = 0; q < 4; q++) acc2[a][i][q] = 0.0f;

    const uint32_t abase = sb + SM_AHI + (uint32_t)(wm*32 + (lane & 15))*APITCH + (uint32_t)(lane >> 4)*16;
    const int roffB = ((lane >> 4) << 3) + (lane & 7);
    const int sgB   = (lane >> 3) & 1;

    for (int ph = 0; ph < 2; ph++) {
        if (ph == 1) {
            __syncthreads();
            load_h_tiles(smem, h_a, row0, t);   // overwrite A with h_a (hi/lo)
            __syncthreads();
        }
        for (int c2 = 0; c2 < 4; c2++) {
            int c = ph*4 + c2;
            if (t < 128) {                      // load merge chunk (single buffer, 8KB)
                uint32_t dst = sb + SM_B + (uint32_t)t*64u;
                const unsigned char* s0 = WU + (size_t)c*8192 + (size_t)t*64;
#pragma unroll
                for (int q = 0; q < 4; q++) CPA16(dst + q*16, s0 + q*16);
            }
            CPCOMMIT(); CPWAIT0();
            __syncthreads();
#pragma unroll
            for (int kk = 0; kk < 2; kk++) {
                uint32_t ah[2][4], al[2][4];
#pragma unroll
                for (int tm = 0; tm < 2; tm++) {
                    ldsm4(ah[tm], abase + (uint32_t)tm*16u*APITCH + (uint32_t)(c2*32 + kk*16)*2);
                    ldsm4(al[tm], abase + 21504u + (uint32_t)tm*16u*APITCH + (uint32_t)(c2*32 + kk*16)*2);
                }
                int n = wn*16 + roffB;
                uint32_t ba = sb + SM_B + (uint32_t)n*64u + (uint32_t)(((2*kk + sgB + (n>>1)) & 3))*16u;
                uint32_t b[4];
                ldsm4(b, ba);
#pragma unroll
                for (int tm = 0; tm < 2; tm++) {
                    mma16816(acc2[tm][0], ah[tm], b);
                    mma16816(acc2[tm][1], ah[tm], b+2);
                    mma16816(acc2[tm][0], al[tm], b);
                    mma16816(acc2[tm][1], al[tm], b+2);
                }
            }
            __syncthreads();
        }
    }

    // final exchange + tanh
    {
        float* exch = (float*)smem;
#pragma unroll
        for (int tm = 0; tm < 2; tm++)
#pragma unroll
            for (int tn = 0; tn < 2; tn++) {
                int col = wn*16 + tn*8 + 2*(lane & 3);
                int r1 = wm*32 + tm*16 + (lane >> 2);
                *(float2*)&exch[r1*132 + col]     = make_float2(acc2[tm][tn][0], acc2[tm][tn][1]);
                *(float2*)&exch[(r1+8)*132 + col] = make_float2(acc2[tm][tn][2], acc2[tm][tn][3]);
            }
        __syncthreads();
        const int row = t >> 3, j0 = (t & 7)*16;
        float* po = h2_out + (size_t)(row0+row)*Hdim + j0;
#pragma unroll
        for (int b = 0; b < 4; b++) {
            int j = j0 + b*4;
            float4 v = *(const float4*)&exch[row*132 + j];
            float4 b1 = *(const float4*)&ufb[j], b2 = *(const float4*)&uab[j];
            float4 out;
            out.x = tanhf(v.x + b1.x + b2.x);
            out.y = tanhf(v.y + b1.y + b2.y);
            out.z = tanhf(v.z + b1.z + b2.z);
            out.w = tanhf(v.w + b1.w + b2.w);
            *(float4*)(po + b*4) = out;
        }
    }
}

// ======== host orchestration ========
struct EmitCtx {
    const float *wpred, *h2o_b, *abi, *abh, *fbi, *fbh, *uab, *ufb;
    const unsigned char *WTC, *WTCF, *WU;
    float *out, *HAI, *H2, *PR;
    int B, idx;
};

static void emit_node(EmitCtx& P, int lvl, int d, const float* h_in) {
    float* probs = P.PR  + (size_t)lvl * P.B * Odim;
    float* h_ai  = P.HAI + (size_t)lvl * P.B * Hdim;
    node_tc<<<P.B / 64, 512, SMEM_TC>>>(h_in, P.wpred, P.h2o_b, P.WTC, P.abi, P.abh,
                                        P.out + (size_t)P.idx * P.B * Odim, probs, h_ai);
    P.idx++;
    if (d > 0) {
        emit_node(P, lvl + 1, d - 1, h_ai);
        float* h2 = P.H2 + (size_t)lvl * P.B * Hdim;
        combine_tc<<<P.B / 64, 512, SMEM_TC>>>(P.PR + (size_t)(lvl+1) * P.B * Odim,
                                               h_ai, h_in, P.WTCF, P.fbi, P.fbh,
                                               P.WU, P.ufb, P.uab, h2);
        emit_node(P, lvl + 1, d - 1, h2);
    }
}

extern "C" void kernel_launch(void* const* d_in, const int* in_sizes, int n_in,
                              void* d_out, int out_size) {
    const float* z     = (const float*)d_in[0];
    const float* z2h_w = (const float*)d_in[1];
    const float* z2h_b = (const float*)d_in[2];
    const float* h2o_w = (const float*)d_in[3];
    const float* h2o_b = (const float*)d_in[4];
    const float* awi   = (const float*)d_in[5];
    const float* abi   = (const float*)d_in[6];
    const float* awh   = (const float*)d_in[7];
    const float* abh   = (const float*)d_in[8];
    const float* fwi   = (const float*)d_in[9];
    const float* fbi   = (const float*)d_in[10];
    const float* fwh   = (const float*)d_in[11];
    const float* fbh   = (const float*)d_in[12];
    const float* uaw   = (const float*)d_in[13];
    const float* uab   = (const float*)d_in[14];
    const float* ufw   = (const float*)d_in[15];
    const float* ufb   = (const float*)d_in[16];

    const int H  = in_sizes[2];
    const int O  = in_sizes[4];
    const int IN = in_sizes[1] / H;
    const int B  = in_sizes[0] / IN;
    const int nn = out_size / (B * O);
    int depth = 0;
    while (((2 << depth) - 1) < nn) depth++;

    float *H0p, *HAIp, *H2p, *PRp, *WPRp;
    unsigned char *WTCp, *WTCFp, *WUp;
    cudaGetSymbolAddress((void**)&H0p,  g_H0);
    cudaGetSymbolAddress((void**)&HAIp, g_HAI);
    cudaGetSymbolAddress((void**)&H2p,  g_H2);
    cudaGetSymbolAddress((void**)&PRp,  g_PR);
    cudaGetSymbolAddress((void**)&WPRp, g_WPRED);
    cudaGetSymbolAddress((void**)&WTCp, g_WTC);
    cudaGetSymbolAddress((void**)&WTCFp, g_WTCF);
    cudaGetSymbolAddress((void**)&WUp,  g_WU);

    cudaFuncSetAttribute(node_tc,    cudaFuncAttributeMaxDynamicSharedMemorySize, SMEM_TC);
    cudaFuncSetAttribute(combine_tc, cudaFuncAttributeMaxDynamicSharedMemorySize, SMEM_TC);

    pack_pred<<<(2048 + 255) / 256, 256>>>(h2o_w, WPRp);
    pack_wtc<<<(6144 + 127) / 128, 128>>>(awh, awi, fwh, fwi, ufw, uaw, WTCp, WTCFp, WUp);
    init_kernel<<<B / RB, NTHR>>>(z, z2h_w, z2h_b, H0p);

    EmitCtx P;
    P.wpred = WPRp; P.h2o_b = h2o_b;
    P.abi = abi; P.abh = abh; P.fbi = fbi; P.fbh = fbh;
    P.uab = uab; P.ufb = ufb;
    P.WTC = WTCp; P.WTCF = WTCFp; P.WU = WUp;
    P.out = (float*)d_out;
    P.HAI = HAIp; P.H2 = H2p; P.PR = PRp;
    P.B = B; P.idx = 0;

    emit_node(P, 0, depth, H0p);
}